// round 12
// baseline (speedup 1.0000x reference)
#include <cuda_runtime.h>
#include <cuda_bf16.h>
#include <math.h>
#include <stdint.h>

#define TSTEPS 5
#define BATCH  128
#define IN0    512
#define HID    1024
#define G4     4096
#define OUTD   32
#define KSPLIT 8

#define BM 128
#define BN 128
#define BK 32
#define NTH 256
#define RS 40            // smem row stride in bf16 (32 data + 8 pad)
#define NCTA 256         // persistent grid size (32 x 8)

// Scratch (device globals; no allocations allowed)
__device__ float g_xg0[TSTEPS * BATCH * G4];
__device__ float g_xg1[TSTEPS * BATCH * G4];
__device__ float g_h1 [TSTEPS * BATCH * HID];
__device__ float g_h2 [TSTEPS * BATCH * HID];
__device__ float g_c  [BATCH * HID];
__device__ __nv_bfloat16 g_hhi[2][BATCH * HID];
__device__ __nv_bfloat16 g_hlo[2][BATCH * HID];
__device__ float g_prt[KSPLIT * BATCH * G4];    // split-K partials, 16 MB
__device__ int   g_arr[24];                     // grid-barrier arrive slots
__device__ int   g_dep[24];                     // grid-barrier depart slots

__device__ __forceinline__ uint32_t smem_u32(const void* p) {
    uint32_t a;
    asm("{ .reg .u64 t; cvta.to.shared.u64 t, %1; cvt.u32.u64 %0, t; }"
        : "=r"(a) : "l"(p));
    return a;
}

#define LDSM_X4(R, addr)                                                     \
    asm volatile("ldmatrix.sync.aligned.m8n8.x4.shared.b16 "                 \
                 "{%0,%1,%2,%3}, [%4];"                                      \
                 : "=r"((R)[0]), "=r"((R)[1]), "=r"((R)[2]), "=r"((R)[3])    \
                 : "r"(addr))
#define LDSM_X2(R, addr)                                                     \
    asm volatile("ldmatrix.sync.aligned.m8n8.x2.shared.b16 {%0,%1}, [%2];"   \
                 : "=r"((R)[0]), "=r"((R)[1]) : "r"(addr))
#define MMA_BF16(D, Ar, Br)                                                  \
    asm volatile("mma.sync.aligned.m16n8k16.row.col.f32.bf16.bf16.f32 "      \
                 "{%0,%1,%2,%3}, {%4,%5,%6,%7}, {%8,%9}, {%0,%1,%2,%3};"     \
                 : "+f"((D)[0]), "+f"((D)[1]), "+f"((D)[2]), "+f"((D)[3])    \
                 : "r"((Ar)[0]), "r"((Ar)[1]), "r"((Ar)[2]), "r"((Ar)[3]),   \
                   "r"((Br)[0]), "r"((Br)[1]))

__device__ __forceinline__ void split_bf16(float f, uint16_t& h, uint16_t& l) {
    __nv_bfloat16 hb = __float2bfloat16(f);
    __nv_bfloat16 lb = __float2bfloat16(f - __bfloat162float(hb));
    h = __bfloat16_as_ushort(hb);
    l = __bfloat16_as_ushort(lb);
}
__device__ __forceinline__ float sigf(float x) { return 1.f / (1.f + expf(-x)); }
// Interleaved gate layout: gathered col q <-> natural W row (q&3)*HID + (q>>2)
__device__ __forceinline__ int icol(int q) { return (q & 3) * HID + (q >> 2); }

// ---------------------------------------------------------------------------
// Bulk tensor-core GEMM (XG precompute), interleaved output columns.
// (proven R7-R11, unchanged)
// ---------------------------------------------------------------------------
__global__ __launch_bounds__(NTH) void hmma_gemm(
    const float* __restrict__ A, const float* __restrict__ W,
    int strideA, int strideW, int ksize,
    const float* __restrict__ b1, const float* __restrict__ b2,
    float* __restrict__ C, int ldc)
{
    __shared__ uint16_t sA[2][2][BM * RS];   // [buf][hi/lo]
    __shared__ uint16_t sW[2][2][BN * RS];

    const int tid  = threadIdx.x;
    const int lane = tid & 31;
    const int warp = tid >> 5;
    const int wm   = warp >> 2;
    const int wn   = warp & 3;
    const int row0 = blockIdx.y * BM;
    const int col0 = blockIdx.x * BN;
    const int nch  = ksize / BK;

    const bool isA = (tid < 128);
    const int  t2  = tid & 127;

    float acc[4][4][4];
#pragma unroll
    for (int i = 0; i < 4; i++)
#pragma unroll
        for (int j = 0; j < 4; j++)
#pragma unroll
            for (int v = 0; v < 4; v++) acc[i][j][v] = 0.f;

    float4 pf[8];
#pragma unroll
    for (int i = 0; i < 8; i++) {
        int idx = t2 + 128 * i;
        int r = idx >> 3, c4 = idx & 7;
        const float* src = isA ? (A + (size_t)(row0 + r) * strideA)
                               : (W + (size_t)icol(col0 + r) * strideW);
        pf[i] = *(const float4*)(src + c4 * 4);
    }
    {
        uint16_t* d0 = isA ? sA[0][0] : sW[0][0];
        uint16_t* d1 = isA ? sA[0][1] : sW[0][1];
#pragma unroll
        for (int i = 0; i < 8; i++) {
            int idx = t2 + 128 * i;
            int r = idx >> 3, c4 = idx & 7;
            float f[4] = {pf[i].x, pf[i].y, pf[i].z, pf[i].w};
            uint16_t h[4], l[4];
#pragma unroll
            for (int j = 0; j < 4; j++) split_bf16(f[j], h[j], l[j]);
            int o = r * RS + c4 * 4;
            *(uint2*)(d0 + o) = *(uint2*)h;
            *(uint2*)(d1 + o) = *(uint2*)l;
        }
    }
    __syncthreads();

    const int rl  = lane & 7;
    const int s8  = (lane >> 3) & 1;
    const int s16 = (lane >> 4) & 1;

    for (int c = 0; c < nch; c++) {
        const int buf = c & 1;
        if (c + 1 < nch) {
            const int kk = (c + 1) * BK;
#pragma unroll
            for (int i = 0; i < 8; i++) {
                int idx = t2 + 128 * i;
                int r = idx >> 3, c4 = idx & 7;
                const float* src = isA ? (A + (size_t)(row0 + r) * strideA)
                                       : (W + (size_t)icol(col0 + r) * strideW);
                pf[i] = *(const float4*)(src + kk + c4 * 4);
            }
        }

        const uint32_t aH = smem_u32(sA[buf][0]);
        const uint32_t aL = smem_u32(sA[buf][1]);
        const uint32_t wH = smem_u32(sW[buf][0]);
        const uint32_t wL = smem_u32(sW[buf][1]);
#pragma unroll
        for (int ks = 0; ks < 2; ks++) {
            const int k0b = (ks * 16 + s8 * 8) * 2;
            const int k0a = (ks * 16 + s16 * 8) * 2;
            uint32_t bh[4][2], bl[4][2];
#pragma unroll
            for (int nt = 0; nt < 4; nt++) {
                uint32_t ro = (uint32_t)(wn * 32 + nt * 8 + rl) * (RS * 2) + k0b;
                LDSM_X2(bh[nt], wH + ro);
                LDSM_X2(bl[nt], wL + ro);
            }
#pragma unroll
            for (int mt = 0; mt < 4; mt++) {
                uint32_t ro = (uint32_t)(wm * 64 + mt * 16 + rl + s8 * 8) * (RS * 2) + k0a;
                uint32_t ah[4], al[4];
                LDSM_X4(ah, aH + ro);
                LDSM_X4(al, aL + ro);
#pragma unroll
                for (int nt = 0; nt < 4; nt++) MMA_BF16(acc[mt][nt], ah, bh[nt]);
#pragma unroll
                for (int nt = 0; nt < 4; nt++) MMA_BF16(acc[mt][nt], ah, bl[nt]);
#pragma unroll
                for (int nt = 0; nt < 4; nt++) MMA_BF16(acc[mt][nt], al, bh[nt]);
            }
        }

        if (c + 1 < nch) {
            uint16_t* d0 = isA ? sA[buf ^ 1][0] : sW[buf ^ 1][0];
            uint16_t* d1 = isA ? sA[buf ^ 1][1] : sW[buf ^ 1][1];
#pragma unroll
            for (int i = 0; i < 8; i++) {
                int idx = t2 + 128 * i;
                int r = idx >> 3, c4 = idx & 7;
                float f[4] = {pf[i].x, pf[i].y, pf[i].z, pf[i].w};
                uint16_t h[4], l[4];
#pragma unroll
                for (int j = 0; j < 4; j++) split_bf16(f[j], h[j], l[j]);
                int o = r * RS + c4 * 4;
                *(uint2*)(d0 + o) = *(uint2*)h;
                *(uint2*)(d1 + o) = *(uint2*)l;
            }
        }
        __syncthreads();
    }

#pragma unroll
    for (int mt = 0; mt < 4; mt++) {
        int row = row0 + wm * 64 + mt * 16 + (lane >> 2);
#pragma unroll
        for (int nt = 0; nt < 4; nt++) {
            int col = col0 + wn * 32 + nt * 8 + (lane & 3) * 2;
            float bb0 = b1[icol(col)] + b2[icol(col)];
            float bb1 = b1[icol(col + 1)] + b2[icol(col + 1)];
            float2 v0 = make_float2(acc[mt][nt][0] + bb0, acc[mt][nt][1] + bb1);
            float2 v1 = make_float2(acc[mt][nt][2] + bb0, acc[mt][nt][3] + bb1);
            *(float2*)(C + (size_t)row * ldc + col) = v0;
            *(float2*)(C + (size_t)(row + 8) * ldc + col) = v1;
        }
    }
}

// ---------------------------------------------------------------------------
// Persistent per-layer LSTM: one launch runs all 5 timesteps.
// Grid (32, 8) = 256 CTAs, 2/SM resident. W stays L1/L2-hot across steps.
// Arrive/depart grid barriers (proven R8-R11 pattern), self-resetting.
// ---------------------------------------------------------------------------
__device__ __forceinline__ void gbar(int slot) {
    __threadfence();
    __syncthreads();
    if (threadIdx.x == 0) {
        atomicAdd(&g_arr[slot], 1);
        while (atomicAdd(&g_arr[slot], 0) < NCTA) __nanosleep(32);
        int d = atomicAdd(&g_dep[slot], 1);
        if (d == NCTA - 1) {
            atomicExch(&g_arr[slot], 0);
            __threadfence();
            atomicExch(&g_dep[slot], 0);
        }
    }
    __syncthreads();
    __threadfence();
}

__global__ __launch_bounds__(NTH, 2) void lstm_layer(
    const float* __restrict__ Whh,
    const float* __restrict__ xg,      // [TSTEPS][BATCH][G4], interleaved cols
    float* __restrict__ hseq,          // [TSTEPS][BATCH][HID]
    int sbase)                         // barrier slot base (layer*12)
{
    __shared__ uint16_t sAh[BM * RS], sAl[BM * RS];
    __shared__ uint16_t sWh[BN * RS], sWl[BN * RS];

    const int tid  = threadIdx.x;
    const int lane = tid & 31;
    const int warp = tid >> 5;
    const int wm   = warp >> 2;
    const int wn   = warp & 3;
    const int bx   = blockIdx.x;
    const int ksl  = blockIdx.y;
    const int kbeg = ksl * (HID / KSPLIT);       // 128
    const int cta  = ksl * 32 + bx;

    const bool isA = (tid < 128);
    const int  t2  = tid & 127;
    const float* ws = Whh + (size_t)icol(bx * BN + t2) * HID + kbeg;

    const int rl  = lane & 7;
    const int s8  = (lane >> 3) & 1;
    const int s16 = (lane >> 4) & 1;
    const uint32_t aH = smem_u32(sAh);
    const uint32_t aL = smem_u32(sAl);
    const uint32_t wH = smem_u32(sWh);
    const uint32_t wL = smem_u32(sWl);

    // ---------------- t = 0: gates only (c_prev = 0) ----------------
#pragma unroll
    for (int i = 0; i < 2; i++) {
        int p = cta * 512 + i * 256 + tid;
        int b = p >> 10;
        int u = p & 1023;
        size_t qb = (size_t)b * G4 + u * 4;
        float4 v = *(const float4*)(xg + qb);
        float cn = sigf(v.x) * tanhf(v.z);
        float hn = sigf(v.w) * tanhf(cn);
        int idx = b * HID + u;
        g_c[idx]  = cn;
        hseq[idx] = hn;
        uint16_t hh, hl;
        split_bf16(hn, hh, hl);
        __stcg((unsigned short*)&g_hhi[0][idx], hh);
        __stcg((unsigned short*)&g_hlo[0][idx], hl);
    }
    gbar(sbase + 0);

    // ---------------- t = 1..4 ----------------
    for (int t = 1; t < TSTEPS; t++) {
        const __nv_bfloat16* hp_hi = g_hhi[(t - 1) & 1];
        const __nv_bfloat16* hp_lo = g_hlo[(t - 1) & 1];
        const __nv_bfloat16* ah = hp_hi + (size_t)t2 * HID + kbeg;
        const __nv_bfloat16* al = hp_lo + (size_t)t2 * HID + kbeg;

        float acc[4][4][4];
#pragma unroll
        for (int i = 0; i < 4; i++)
#pragma unroll
            for (int j = 0; j < 4; j++)
#pragma unroll
                for (int v = 0; v < 4; v++) acc[i][j][v] = 0.f;

        const int nch = (HID / KSPLIT) / BK;     // 4
        for (int c = 0; c < nch; c++) {
            const int kk = c * BK;
            if (isA) {
#pragma unroll
                for (int hf = 0; hf < 2; hf++) {
                    uint4 u0 = __ldcg((const uint4*)(ah + kk + hf * 16));
                    uint4 u1 = __ldcg((const uint4*)(ah + kk + hf * 16 + 8));
                    uint4 v0 = __ldcg((const uint4*)(al + kk + hf * 16));
                    uint4 v1 = __ldcg((const uint4*)(al + kk + hf * 16 + 8));
                    int o = t2 * RS + hf * 16;
                    *(uint4*)(sAh + o)     = u0;
                    *(uint4*)(sAh + o + 8) = u1;
                    *(uint4*)(sAl + o)     = v0;
                    *(uint4*)(sAl + o + 8) = v1;
                }
            } else {
#pragma unroll
                for (int hf = 0; hf < 2; hf++) {
                    float4 f0 = *(const float4*)(ws + kk + hf * 16);
                    float4 f1 = *(const float4*)(ws + kk + hf * 16 + 4);
                    float4 f2 = *(const float4*)(ws + kk + hf * 16 + 8);
                    float4 f3 = *(const float4*)(ws + kk + hf * 16 + 12);
                    float f[16] = {f0.x, f0.y, f0.z, f0.w, f1.x, f1.y, f1.z, f1.w,
                                   f2.x, f2.y, f2.z, f2.w, f3.x, f3.y, f3.z, f3.w};
                    uint16_t h[16], l[16];
#pragma unroll
                    for (int j = 0; j < 16; j++) split_bf16(f[j], h[j], l[j]);
                    int o = t2 * RS + hf * 16;
                    *(uint4*)(sWh + o)     = ((uint4*)h)[0];
                    *(uint4*)(sWh + o + 8) = ((uint4*)h)[1];
                    *(uint4*)(sWl + o)     = ((uint4*)l)[0];
                    *(uint4*)(sWl + o + 8) = ((uint4*)l)[1];
                }
            }
            __syncthreads();

#pragma unroll
            for (int ks = 0; ks < 2; ks++) {
                const int k0b = (ks * 16 + s8 * 8) * 2;
                const int k0a = (ks * 16 + s16 * 8) * 2;
                uint32_t bh[4][2], bl[4][2];
#pragma unroll
                for (int nt = 0; nt < 4; nt++) {
                    uint32_t ro = (uint32_t)(wn * 32 + nt * 8 + rl) * (RS * 2) + k0b;
                    LDSM_X2(bh[nt], wH + ro);
                    LDSM_X2(bl[nt], wL + ro);
                }
#pragma unroll
                for (int mt = 0; mt < 4; mt++) {
                    uint32_t ro = (uint32_t)(wm * 64 + mt * 16 + rl + s8 * 8) * (RS * 2) + k0a;
                    uint32_t ahf[4], alf[4];
                    LDSM_X4(ahf, aH + ro);
                    LDSM_X4(alf, aL + ro);
#pragma unroll
                    for (int nt = 0; nt < 4; nt++) MMA_BF16(acc[mt][nt], ahf, bh[nt]);
#pragma unroll
                    for (int nt = 0; nt < 4; nt++) MMA_BF16(acc[mt][nt], ahf, bl[nt]);
#pragma unroll
                    for (int nt = 0; nt < 4; nt++) MMA_BF16(acc[mt][nt], alf, bh[nt]);
                }
            }
            __syncthreads();
        }

        // store partial tile (plain st -> L2 write-through for cross-CTA read)
        float* myp = g_prt + (size_t)ksl * BATCH * G4;
#pragma unroll
        for (int mt = 0; mt < 4; mt++) {
            int row = wm * 64 + mt * 16 + (lane >> 2);
#pragma unroll
            for (int nt = 0; nt < 4; nt++) {
                int col = bx * BN + wn * 32 + nt * 8 + (lane & 3) * 2;
                __stcg((float2*)(myp + (size_t)row * G4 + col),
                       make_float2(acc[mt][nt][0], acc[mt][nt][1]));
                __stcg((float2*)(myp + (size_t)(row + 8) * G4 + col),
                       make_float2(acc[mt][nt][2], acc[mt][nt][3]));
            }
        }

        gbar(sbase + 2 * t - 1);

        // gates phase
        const float* xgt = xg + (size_t)t * BATCH * G4;
        float* ht = hseq + (size_t)t * BATCH * HID;
        __nv_bfloat16* ho_hi = g_hhi[t & 1];
        __nv_bfloat16* ho_lo = g_hlo[t & 1];
#pragma unroll
        for (int i = 0; i < 2; i++) {
            int p = cta * 512 + i * 256 + tid;
            int b = p >> 10;
            int u = p & 1023;
            size_t qb = (size_t)b * G4 + u * 4;
            float4 v = *(const float4*)(xgt + qb);
#pragma unroll
            for (int s = 0; s < KSPLIT; s++) {
                float4 pp = __ldcg((const float4*)(g_prt + (size_t)s * BATCH * G4 + qb));
                v.x += pp.x; v.y += pp.y; v.z += pp.z; v.w += pp.w;
            }
            int idx = b * HID + u;
            float cp = g_c[idx];
            float cn = sigf(v.y) * cp + sigf(v.x) * tanhf(v.z);
            float hn = sigf(v.w) * tanhf(cn);
            g_c[idx] = cn;
            ht[idx]  = hn;
            uint16_t hh, hl;
            split_bf16(hn, hh, hl);
            __stcg((unsigned short*)&ho_hi[idx], hh);
            __stcg((unsigned short*)&ho_lo[idx], hl);
        }

        if (t < TSTEPS - 1) gbar(sbase + 2 * t);
    }
}

// ---------------------------------------------------------------------------
// Head: out[b,o] = dot(h2[4][b,:], Wout[o,:]) + bout[o]
// ---------------------------------------------------------------------------
__global__ __launch_bounds__(256) void head_kernel(
    const float* __restrict__ hfin,
    const float* __restrict__ Wout, const float* __restrict__ bout,
    float* __restrict__ out)
{
    __shared__ float hs[HID];
    __shared__ float red[8][32];
    int b = blockIdx.x;
    for (int i = threadIdx.x; i < HID; i += 256) hs[i] = hfin[(size_t)b * HID + i];
    __syncthreads();

    int o     = threadIdx.x % 32;
    int chunk = threadIdx.x / 32;
    float s = 0.f;
    const float* wrow = Wout + (size_t)o * HID;
#pragma unroll 4
    for (int k = chunk * 128; k < chunk * 128 + 128; k++)
        s = fmaf(hs[k], wrow[k], s);
    red[chunk][o] = s;
    __syncthreads();

    if (threadIdx.x < 32) {
        float t = 0.f;
#pragma unroll
        for (int ch = 0; ch < 8; ch++) t += red[ch][threadIdx.x];
        out[(size_t)b * OUTD + threadIdx.x] = t + bout[threadIdx.x];
    }
}

// ---------------------------------------------------------------------------
// Host launcher (5 launches)
// ---------------------------------------------------------------------------
extern "C" void kernel_launch(void* const* d_in, const int* in_sizes, int n_in,
                              void* d_out, int out_size)
{
    const float* input = (const float*)d_in[0];
    const float* w_ih0 = (const float*)d_in[1];
    const float* w_hh0 = (const float*)d_in[2];
    const float* b_ih0 = (const float*)d_in[3];
    const float* b_hh0 = (const float*)d_in[4];
    const float* w_ih1 = (const float*)d_in[5];
    const float* w_hh1 = (const float*)d_in[6];
    const float* b_ih1 = (const float*)d_in[7];
    const float* b_hh1 = (const float*)d_in[8];
    const float* w_out = (const float*)d_in[9];
    const float* b_out = (const float*)d_in[10];
    float* out = (float*)d_out;

    float *xg0, *xg1, *h1, *h2;
    cudaGetSymbolAddress((void**)&xg0, g_xg0);
    cudaGetSymbolAddress((void**)&xg1, g_xg1);
    cudaGetSymbolAddress((void**)&h1,  g_h1);
    cudaGetSymbolAddress((void**)&h2,  g_h2);

    const size_t BH = (size_t)BATCH * HID;

    // 1) XG0 = input[0:640] @ w_ih0^T (interleaved cols) + biases
    {
        dim3 grid(G4 / BN, TSTEPS * BATCH / BM);
        hmma_gemm<<<grid, NTH>>>(input, w_ih0, IN0, IN0, IN0,
                                 b_ih0, b_hh0, xg0, G4);
    }
    // 2) Layer-0: all 5 timesteps in one persistent launch
    lstm_layer<<<dim3(32, KSPLIT), NTH>>>(w_hh0, xg0, h1, 0);

    // 3) XG1 = h1 @ w_ih1^T (interleaved cols) + biases
    {
        dim3 grid(G4 / BN, TSTEPS * BATCH / BM);
        hmma_gemm<<<grid, NTH>>>(h1, w_ih1, HID, HID, HID,
                                 b_ih1, b_hh1, xg1, G4);
    }
    // 4) Layer-1
    lstm_layer<<<dim3(32, KSPLIT), NTH>>>(w_hh1, xg1, h2, 12);

    // 5) Linear head on h2[4]
    head_kernel<<<BATCH, 256>>>(h2 + (size_t)4 * BH, w_out, b_out, out);
}

// round 13
// speedup vs baseline: 1.5131x; 1.5131x over previous
#include <cuda_runtime.h>
#include <cuda_fp16.h>
#include <math.h>
#include <stdint.h>

#define TSTEPS 5
#define BATCH  128
#define IN0    512
#define HID    1024
#define G4     4096
#define OUTD   32
#define SPLITK 4

#define BM 128
#define BN 128
#define BK 32
#define NTH 256
#define RS 40            // smem row stride in fp16 (32 data + 8 pad)

// Scratch (device globals; no allocations allowed)
__device__ float g_xg0[TSTEPS * BATCH * G4];
__device__ float g_xg1[TSTEPS * BATCH * G4];
__device__ float g_h1 [TSTEPS * BATCH * HID];
__device__ float g_h  [BATCH * HID];
__device__ float g_c  [BATCH * HID];
__device__ float g_part[SPLITK * BATCH * G4];

__device__ __forceinline__ uint32_t smem_u32(const void* p) {
    uint32_t a;
    asm("{ .reg .u64 t; cvta.to.shared.u64 t, %1; cvt.u32.u64 %0, t; }"
        : "=r"(a) : "l"(p));
    return a;
}

#define LDSM_X4(R, addr)                                                     \
    asm volatile("ldmatrix.sync.aligned.m8n8.x4.shared.b16 "                 \
                 "{%0,%1,%2,%3}, [%4];"                                      \
                 : "=r"((R)[0]), "=r"((R)[1]), "=r"((R)[2]), "=r"((R)[3])    \
                 : "r"(addr))
#define LDSM_X2(R, addr)                                                     \
    asm volatile("ldmatrix.sync.aligned.m8n8.x2.shared.b16 {%0,%1}, [%2];"   \
                 : "=r"((R)[0]), "=r"((R)[1]) : "r"(addr))
#define MMA_F16(D, Ar, Br)                                                   \
    asm volatile("mma.sync.aligned.m16n8k16.row.col.f32.f16.f16.f32 "        \
                 "{%0,%1,%2,%3}, {%4,%5,%6,%7}, {%8,%9}, {%0,%1,%2,%3};"     \
                 : "+f"((D)[0]), "+f"((D)[1]), "+f"((D)[2]), "+f"((D)[3])    \
                 : "r"((Ar)[0]), "r"((Ar)[1]), "r"((Ar)[2]), "r"((Ar)[3]),   \
                   "r"((Br)[0]), "r"((Br)[1]))

// W split: fp16 hi + lo (~22 effective mantissa bits)
__device__ __forceinline__ void split_h16(float f, uint16_t& h, uint16_t& l) {
    __half hb = __float2half_rn(f);
    __half lb = __float2half_rn(f - __half2float(hb));
    h = __half_as_ushort(hb);
    l = __half_as_ushort(lb);
}
__device__ __forceinline__ uint16_t to_h16(float f) {
    return __half_as_ushort(__float2half_rn(f));
}
__device__ __forceinline__ float sigf(float x) { return 1.f / (1.f + expf(-x)); }

// ---------------------------------------------------------------------------
// Tensor-core GEMM: C[M, N] (+bias) = A[*,K] @ W[N,K]^T
// A single fp16; W split fp16 hi/lo; 2 MMAs per k-step (a*wh + a*wl).
// blockIdx: x = N-tile (128), y = M-tile (128), z = split-K slice.
// ---------------------------------------------------------------------------
__global__ __launch_bounds__(NTH) void hmma_gemm(
    const float* __restrict__ A, const float* __restrict__ W,
    int strideA, int strideW, int ksize,
    const float* __restrict__ b1, const float* __restrict__ b2,
    float* __restrict__ Cbase, int ldc, int zStride)
{
    __shared__ uint16_t sA[BM * RS];        // A: single fp16 copy
    __shared__ uint16_t sW[2][BN * RS];     // W: hi/lo

    const int tid  = threadIdx.x;
    const int lane = tid & 31;
    const int warp = tid >> 5;
    const int wm   = warp >> 2;           // 0..1
    const int wn   = warp & 3;            // 0..3
    const int row0 = blockIdx.y * BM;
    const int col0 = blockIdx.x * BN;
    const int kbeg = blockIdx.z * ksize;
    const int nch  = ksize / BK;

    const bool isA = (tid < 128);
    const int  t2  = tid & 127;
    const float* src = isA ? (A + (size_t)row0 * strideA)
                           : (W + (size_t)col0 * strideW);
    const int sstr = isA ? strideA : strideW;

    float4 pf[8];
    const uint32_t bA  = smem_u32(sA);
    const uint32_t bW0 = smem_u32(sW[0]);
    const uint32_t bW1 = smem_u32(sW[1]);

    float acc[4][4][4];
#pragma unroll
    for (int i = 0; i < 4; i++)
#pragma unroll
        for (int j = 0; j < 4; j++)
#pragma unroll
            for (int v = 0; v < 4; v++) acc[i][j][v] = 0.f;

    // load chunk 0 into regs
#pragma unroll
    for (int i = 0; i < 8; i++) {
        int idx = t2 + 128 * i;           // 0..1023 float4 slots
        int r = idx >> 3, c4 = idx & 7;
        pf[i] = *(const float4*)(src + (size_t)r * sstr + kbeg + c4 * 4);
    }

    const int rl  = lane & 7;
    const int s8  = (lane >> 3) & 1;
    const int s16 = (lane >> 4) & 1;

    for (int c = 0; c < nch; c++) {
        // store regs -> smem
        if (isA) {
#pragma unroll
            for (int i = 0; i < 8; i++) {
                int idx = t2 + 128 * i;
                int r = idx >> 3, c4 = idx & 7;
                float f[4] = {pf[i].x, pf[i].y, pf[i].z, pf[i].w};
                uint16_t a[4];
#pragma unroll
                for (int j = 0; j < 4; j++) a[j] = to_h16(f[j]);
                *(uint2*)(sA + r * RS + c4 * 4) = *(uint2*)a;
            }
        } else {
#pragma unroll
            for (int i = 0; i < 8; i++) {
                int idx = t2 + 128 * i;
                int r = idx >> 3, c4 = idx & 7;
                float f[4] = {pf[i].x, pf[i].y, pf[i].z, pf[i].w};
                uint16_t h[4], l[4];
#pragma unroll
                for (int j = 0; j < 4; j++) split_h16(f[j], h[j], l[j]);
                int o = r * RS + c4 * 4;
                *(uint2*)(sW[0] + o) = *(uint2*)h;
                *(uint2*)(sW[1] + o) = *(uint2*)l;
            }
        }
        __syncthreads();

        // prefetch next chunk (overlaps MMA stream)
        if (c + 1 < nch) {
            const int kk = kbeg + (c + 1) * BK;
#pragma unroll
            for (int i = 0; i < 8; i++) {
                int idx = t2 + 128 * i;
                int r = idx >> 3, c4 = idx & 7;
                pf[i] = *(const float4*)(src + (size_t)r * sstr + kk + c4 * 4);
            }
        }

        // compute: 2 k-steps of 16
#pragma unroll
        for (int ks = 0; ks < 2; ks++) {
            const int k0b = (ks * 16 + s8 * 8) * 2;
            const int k0a = (ks * 16 + s16 * 8) * 2;

            uint32_t bh[4][2], bl[4][2];
#pragma unroll
            for (int nt = 0; nt < 4; nt++) {
                uint32_t ro = (uint32_t)(wn * 32 + nt * 8 + rl) * (RS * 2) + k0b;
                LDSM_X2(bh[nt], bW0 + ro);
                LDSM_X2(bl[nt], bW1 + ro);
            }
#pragma unroll
            for (int mt = 0; mt < 4; mt++) {
                uint32_t ro = (uint32_t)(wm * 64 + mt * 16 + rl + s8 * 8) * (RS * 2) + k0a;
                uint32_t ah[4];
                LDSM_X4(ah, bA + ro);
#pragma unroll
                for (int nt = 0; nt < 4; nt++) MMA_F16(acc[mt][nt], ah, bh[nt]);
#pragma unroll
                for (int nt = 0; nt < 4; nt++) MMA_F16(acc[mt][nt], ah, bl[nt]);
            }
        }
        __syncthreads();
    }

    // Epilogue: direct fragment stores (+bias)
    float* outp = Cbase + (size_t)blockIdx.z * zStride;
#pragma unroll
    for (int mt = 0; mt < 4; mt++) {
        int row = row0 + wm * 64 + mt * 16 + (lane >> 2);
#pragma unroll
        for (int nt = 0; nt < 4; nt++) {
            int col = col0 + wn * 32 + nt * 8 + (lane & 3) * 2;
            float bb0 = 0.f, bb1 = 0.f;
            if (b1) {
                bb0 = b1[col] + b2[col];
                bb1 = b1[col + 1] + b2[col + 1];
            }
            float2 v0 = make_float2(acc[mt][nt][0] + bb0, acc[mt][nt][1] + bb1);
            float2 v1 = make_float2(acc[mt][nt][2] + bb0, acc[mt][nt][3] + bb1);
            *(float2*)(outp + (size_t)row * ldc + col) = v0;
            *(float2*)(outp + (size_t)(row + 8) * ldc + col) = v1;
        }
    }
}

// ---------------------------------------------------------------------------
// Gate fusion (float4): g = xg + sum split-K partials; order i,f,g,o
// ---------------------------------------------------------------------------
__global__ __launch_bounds__(256) void gates_kernel(
    const float* __restrict__ xg, float* __restrict__ hseq, int first)
{
    int q  = blockIdx.x * blockDim.x + threadIdx.x;
    int b  = q / (HID / 4);
    int j4 = (q % (HID / 4)) * 4;
    size_t base = (size_t)b * G4 + j4;

    float4 gi = *(const float4*)(xg + base);
    float4 gf = *(const float4*)(xg + base + HID);
    float4 gg = *(const float4*)(xg + base + 2 * HID);
    float4 go = *(const float4*)(xg + base + 3 * HID);

    if (!first) {
#pragma unroll
        for (int s = 0; s < SPLITK; s++) {
            const float* P = g_part + (size_t)s * BATCH * G4 + base;
            float4 p;
            p = *(const float4*)(P);           gi.x += p.x; gi.y += p.y; gi.z += p.z; gi.w += p.w;
            p = *(const float4*)(P + HID);     gf.x += p.x; gf.y += p.y; gf.z += p.z; gf.w += p.w;
            p = *(const float4*)(P + 2 * HID); gg.x += p.x; gg.y += p.y; gg.z += p.z; gg.w += p.w;
            p = *(const float4*)(P + 3 * HID); go.x += p.x; go.y += p.y; go.z += p.z; go.w += p.w;
        }
    }

    int idx = b * HID + j4;
    float4 cp = first ? make_float4(0.f, 0.f, 0.f, 0.f) : *(const float4*)(g_c + idx);

    float ci[4] = {gi.x, gi.y, gi.z, gi.w};
    float cf[4] = {gf.x, gf.y, gf.z, gf.w};
    float cg[4] = {gg.x, gg.y, gg.z, gg.w};
    float co[4] = {go.x, go.y, go.z, go.w};
    float cpv[4] = {cp.x, cp.y, cp.z, cp.w};
    float cv[4], hv[4];
#pragma unroll
    for (int j = 0; j < 4; j++) {
        cv[j] = sigf(cf[j]) * cpv[j] + sigf(ci[j]) * tanhf(cg[j]);
        hv[j] = sigf(co[j]) * tanhf(cv[j]);
    }
    *(float4*)(g_c + idx) = make_float4(cv[0], cv[1], cv[2], cv[3]);
    float4 hout = make_float4(hv[0], hv[1], hv[2], hv[3]);
    *(float4*)(g_h + idx) = hout;
    if (hseq) *(float4*)(hseq + idx) = hout;
}

// ---------------------------------------------------------------------------
// Head: out[b,o] = dot(h_final[b,:], Wout[o,:]) + bout[o]
// ---------------------------------------------------------------------------
__global__ __launch_bounds__(256) void head_kernel(
    const float* __restrict__ Wout, const float* __restrict__ bout,
    float* __restrict__ out)
{
    __shared__ float hs[HID];
    __shared__ float red[8][32];
    int b = blockIdx.x;
    for (int i = threadIdx.x; i < HID; i += 256) hs[i] = g_h[(size_t)b * HID + i];
    __syncthreads();

    int o     = threadIdx.x % 32;
    int chunk = threadIdx.x / 32;
    float s = 0.f;
    const float* wrow = Wout + (size_t)o * HID;
#pragma unroll 4
    for (int k = chunk * 128; k < chunk * 128 + 128; k++)
        s = fmaf(hs[k], wrow[k], s);
    red[chunk][o] = s;
    __syncthreads();

    if (threadIdx.x < 32) {
        float t = 0.f;
#pragma unroll
        for (int ch = 0; ch < 8; ch++) t += red[ch][threadIdx.x];
        out[(size_t)b * OUTD + threadIdx.x] = t + bout[threadIdx.x];
    }
}

// ---------------------------------------------------------------------------
// Host launcher (identical structure to the 324 us R3 best)
// ---------------------------------------------------------------------------
extern "C" void kernel_launch(void* const* d_in, const int* in_sizes, int n_in,
                              void* d_out, int out_size)
{
    const float* input = (const float*)d_in[0];
    const float* w_ih0 = (const float*)d_in[1];
    const float* w_hh0 = (const float*)d_in[2];
    const float* b_ih0 = (const float*)d_in[3];
    const float* b_hh0 = (const float*)d_in[4];
    const float* w_ih1 = (const float*)d_in[5];
    const float* w_hh1 = (const float*)d_in[6];
    const float* b_ih1 = (const float*)d_in[7];
    const float* b_hh1 = (const float*)d_in[8];
    const float* w_out = (const float*)d_in[9];
    const float* b_out = (const float*)d_in[10];
    float* out = (float*)d_out;

    float *xg0, *xg1, *h1, *h, *part;
    cudaGetSymbolAddress((void**)&xg0,  g_xg0);
    cudaGetSymbolAddress((void**)&xg1,  g_xg1);
    cudaGetSymbolAddress((void**)&h1,   g_h1);
    cudaGetSymbolAddress((void**)&h,    g_h);
    cudaGetSymbolAddress((void**)&part, g_part);

    const int KSLICE = HID / SPLITK;   // 256
    const int ZSTR   = BATCH * G4;

    // 1) Layer-0 input gates: [640,4096] = input[0:640,512] @ w_ih0^T + biases
    {
        dim3 grid(G4 / BN, TSTEPS * BATCH / BM, 1);
        hmma_gemm<<<grid, NTH>>>(input, w_ih0, IN0, IN0, IN0,
                                 b_ih0, b_hh0, xg0, G4, 0);
    }
    // 2) Layer-0 recurrence
    for (int t = 0; t < TSTEPS; t++) {
        if (t > 0) {
            dim3 grid(G4 / BN, 1, SPLITK);
            hmma_gemm<<<grid, NTH>>>(h, w_hh0, HID, HID, KSLICE,
                                     (const float*)0, (const float*)0,
                                     part, G4, ZSTR);
        }
        gates_kernel<<<(BATCH * HID / 4) / 256, 256>>>(
            xg0 + (size_t)t * BATCH * G4, h1 + (size_t)t * BATCH * HID, t == 0);
    }
    // 3) Layer-1 input gates: [640,4096] = h1 @ w_ih1^T + biases
    {
        dim3 grid(G4 / BN, TSTEPS * BATCH / BM, 1);
        hmma_gemm<<<grid, NTH>>>(h1, w_ih1, HID, HID, HID,
                                 b_ih1, b_hh1, xg1, G4, 0);
    }
    // 4) Layer-1 recurrence
    for (int t = 0; t < TSTEPS; t++) {
        if (t > 0) {
            dim3 grid(G4 / BN, 1, SPLITK);
            hmma_gemm<<<grid, NTH>>>(h, w_hh1, HID, HID, KSLICE,
                                     (const float*)0, (const float*)0,
                                     part, G4, ZSTR);
        }
        gates_kernel<<<(BATCH * HID / 4) / 256, 256>>>(
            xg1 + (size_t)t * BATCH * G4, (float*)0, t == 0);
    }
    // 5) Linear head on h2[4]
    head_kernel<<<BATCH, 256>>>(w_out, b_out, out);
}

// round 14
// speedup vs baseline: 2.1156x; 1.3982x over previous
#include <cuda_runtime.h>
#include <cuda_fp16.h>
#include <math.h>
#include <stdint.h>

#define TSTEPS 5
#define BATCH  128
#define IN0    512
#define HID    1024
#define G4     4096
#define OUTD   32
#define SPLITK 4

#define BM 128
#define BN 128
#define BK 32
#define NTH 256
#define RS 40            // smem row stride in fp16 (32 data + 8 pad)

// Scratch (device globals; no allocations allowed)
__device__ float g_xg0[TSTEPS * BATCH * G4];
__device__ float g_xg1[TSTEPS * BATCH * G4];
__device__ float g_h1 [TSTEPS * BATCH * HID];
__device__ float g_h  [BATCH * HID];
__device__ float g_c  [BATCH * HID];
__device__ float g_part[SPLITK * BATCH * G4];

__device__ __forceinline__ uint32_t smem_u32(const void* p) {
    uint32_t a;
    asm("{ .reg .u64 t; cvta.to.shared.u64 t, %1; cvt.u32.u64 %0, t; }"
        : "=r"(a) : "l"(p));
    return a;
}

#define LDSM_X4(R, addr)                                                     \
    asm volatile("ldmatrix.sync.aligned.m8n8.x4.shared.b16 "                 \
                 "{%0,%1,%2,%3}, [%4];"                                      \
                 : "=r"((R)[0]), "=r"((R)[1]), "=r"((R)[2]), "=r"((R)[3])    \
                 : "r"(addr))
#define LDSM_X2(R, addr)                                                     \
    asm volatile("ldmatrix.sync.aligned.m8n8.x2.shared.b16 {%0,%1}, [%2];"   \
                 : "=r"((R)[0]), "=r"((R)[1]) : "r"(addr))
#define MMA_F16(D, Ar, Br)                                                   \
    asm volatile("mma.sync.aligned.m16n8k16.row.col.f32.f16.f16.f32 "        \
                 "{%0,%1,%2,%3}, {%4,%5,%6,%7}, {%8,%9}, {%0,%1,%2,%3};"     \
                 : "+f"((D)[0]), "+f"((D)[1]), "+f"((D)[2]), "+f"((D)[3])    \
                 : "r"((Ar)[0]), "r"((Ar)[1]), "r"((Ar)[2]), "r"((Ar)[3]),   \
                   "r"((Br)[0]), "r"((Br)[1]))

__device__ __forceinline__ uint16_t to_h16(float f) {
    return __half_as_ushort(__float2half_rn(f));
}
__device__ __forceinline__ float sigf(float x) { return 1.f / (1.f + expf(-x)); }

// ---------------------------------------------------------------------------
// Tensor-core GEMM: C[M, N] (+bias) = A[*,K] @ W[N,K]^T
// A and W single fp16; ONE MMA per (mt, nt, k-step).
// blockIdx: x = N-tile (128), y = M-tile (128), z = split-K slice.
// ---------------------------------------------------------------------------
__global__ __launch_bounds__(NTH) void hmma_gemm(
    const float* __restrict__ A, const float* __restrict__ W,
    int strideA, int strideW, int ksize,
    const float* __restrict__ b1, const float* __restrict__ b2,
    float* __restrict__ Cbase, int ldc, int zStride)
{
    __shared__ uint16_t sA[BM * RS];
    __shared__ uint16_t sW[BN * RS];

    const int tid  = threadIdx.x;
    const int lane = tid & 31;
    const int warp = tid >> 5;
    const int wm   = warp >> 2;           // 0..1
    const int wn   = warp & 3;            // 0..3
    const int row0 = blockIdx.y * BM;
    const int col0 = blockIdx.x * BN;
    const int kbeg = blockIdx.z * ksize;
    const int nch  = ksize / BK;

    const bool isA = (tid < 128);
    const int  t2  = tid & 127;
    const float* src = isA ? (A + (size_t)row0 * strideA)
                           : (W + (size_t)col0 * strideW);
    const int sstr = isA ? strideA : strideW;
    uint16_t* dst = isA ? sA : sW;

    float4 pf[8];
    const uint32_t bA = smem_u32(sA);
    const uint32_t bW = smem_u32(sW);

    float acc[4][4][4];
#pragma unroll
    for (int i = 0; i < 4; i++)
#pragma unroll
        for (int j = 0; j < 4; j++)
#pragma unroll
            for (int v = 0; v < 4; v++) acc[i][j][v] = 0.f;

    // load chunk 0 into regs
#pragma unroll
    for (int i = 0; i < 8; i++) {
        int idx = t2 + 128 * i;           // 0..1023 float4 slots
        int r = idx >> 3, c4 = idx & 7;
        pf[i] = *(const float4*)(src + (size_t)r * sstr + kbeg + c4 * 4);
    }

    const int rl  = lane & 7;
    const int s8  = (lane >> 3) & 1;
    const int s16 = (lane >> 4) & 1;

    for (int c = 0; c < nch; c++) {
        // store regs -> smem (fp16)
#pragma unroll
        for (int i = 0; i < 8; i++) {
            int idx = t2 + 128 * i;
            int r = idx >> 3, c4 = idx & 7;
            float f[4] = {pf[i].x, pf[i].y, pf[i].z, pf[i].w};
            uint16_t a[4];
#pragma unroll
            for (int j = 0; j < 4; j++) a[j] = to_h16(f[j]);
            *(uint2*)(dst + r * RS + c4 * 4) = *(uint2*)a;
        }
        __syncthreads();

        // prefetch next chunk (overlaps MMA stream)
        if (c + 1 < nch) {
            const int kk = kbeg + (c + 1) * BK;
#pragma unroll
            for (int i = 0; i < 8; i++) {
                int idx = t2 + 128 * i;
                int r = idx >> 3, c4 = idx & 7;
                pf[i] = *(const float4*)(src + (size_t)r * sstr + kk + c4 * 4);
            }
        }

        // compute: 2 k-steps of 16, single MMA each
#pragma unroll
        for (int ks = 0; ks < 2; ks++) {
            const int k0b = (ks * 16 + s8 * 8) * 2;
            const int k0a = (ks * 16 + s16 * 8) * 2;

            uint32_t bw[4][2];
#pragma unroll
            for (int nt = 0; nt < 4; nt++) {
                uint32_t ro = (uint32_t)(wn * 32 + nt * 8 + rl) * (RS * 2) + k0b;
                LDSM_X2(bw[nt], bW + ro);
            }
#pragma unroll
            for (int mt = 0; mt < 4; mt++) {
                uint32_t ro = (uint32_t)(wm * 64 + mt * 16 + rl + s8 * 8) * (RS * 2) + k0a;
                uint32_t ah[4];
                LDSM_X4(ah, bA + ro);
#pragma unroll
                for (int nt = 0; nt < 4; nt++) MMA_F16(acc[mt][nt], ah, bw[nt]);
            }
        }
        __syncthreads();
    }

    // Epilogue: direct fragment stores (+bias)
    float* outp = Cbase + (size_t)blockIdx.z * zStride;
#pragma unroll
    for (int mt = 0; mt < 4; mt++) {
        int row = row0 + wm * 64 + mt * 16 + (lane >> 2);
#pragma unroll
        for (int nt = 0; nt < 4; nt++) {
            int col = col0 + wn * 32 + nt * 8 + (lane & 3) * 2;
            float bb0 = 0.f, bb1 = 0.f;
            if (b1) {
                bb0 = b1[col] + b2[col];
                bb1 = b1[col + 1] + b2[col + 1];
            }
            float2 v0 = make_float2(acc[mt][nt][0] + bb0, acc[mt][nt][1] + bb1);
            float2 v1 = make_float2(acc[mt][nt][2] + bb0, acc[mt][nt][3] + bb1);
            *(float2*)(outp + (size_t)row * ldc + col) = v0;
            *(float2*)(outp + (size_t)(row + 8) * ldc + col) = v1;
        }
    }
}

// ---------------------------------------------------------------------------
// Gate fusion: 512 blocks, one unit per thread (scalar coalesced loads).
// g = xg + sum split-K partials; order i,f,g,o
// ---------------------------------------------------------------------------
__global__ __launch_bounds__(256) void gates_kernel(
    const float* __restrict__ xg, float* __restrict__ hseq, int first)
{
    int q = blockIdx.x * 256 + threadIdx.x;   // 0..BATCH*HID-1
    int b = q >> 10;
    int j = q & 1023;
    size_t base = (size_t)b * G4 + j;

    float gi = xg[base];
    float gf = xg[base + HID];
    float gg = xg[base + 2 * HID];
    float go = xg[base + 3 * HID];

    if (!first) {
#pragma unroll
        for (int s = 0; s < SPLITK; s++) {
            const float* P = g_part + (size_t)s * BATCH * G4 + base;
            gi += P[0];
            gf += P[HID];
            gg += P[2 * HID];
            go += P[3 * HID];
        }
    }

    int idx = b * HID + j;
    float cp = first ? 0.f : g_c[idx];
    float cn = sigf(gf) * cp + sigf(gi) * tanhf(gg);
    float hn = sigf(go) * tanhf(cn);
    g_c[idx] = cn;
    g_h[idx] = hn;
    if (hseq) hseq[idx] = hn;
}

// ---------------------------------------------------------------------------
// Head: out[b,o] = dot(h_final[b,:], Wout[o,:]) + bout[o]
// ---------------------------------------------------------------------------
__global__ __launch_bounds__(256) void head_kernel(
    const float* __restrict__ Wout, const float* __restrict__ bout,
    float* __restrict__ out)
{
    __shared__ float hs[HID];
    __shared__ float red[8][32];
    int b = blockIdx.x;
    for (int i = threadIdx.x; i < HID; i += 256) hs[i] = g_h[(size_t)b * HID + i];
    __syncthreads();

    int o     = threadIdx.x % 32;
    int chunk = threadIdx.x / 32;
    float s = 0.f;
    const float* wrow = Wout + (size_t)o * HID;
#pragma unroll 4
    for (int k = chunk * 128; k < chunk * 128 + 128; k++)
        s = fmaf(hs[k], wrow[k], s);
    red[chunk][o] = s;
    __syncthreads();

    if (threadIdx.x < 32) {
        float t = 0.f;
#pragma unroll
        for (int ch = 0; ch < 8; ch++) t += red[ch][threadIdx.x];
        out[(size_t)b * OUTD + threadIdx.x] = t + bout[threadIdx.x];
    }
}

// ---------------------------------------------------------------------------
// Host launcher
// ---------------------------------------------------------------------------
extern "C" void kernel_launch(void* const* d_in, const int* in_sizes, int n_in,
                              void* d_out, int out_size)
{
    const float* input = (const float*)d_in[0];
    const float* w_ih0 = (const float*)d_in[1];
    const float* w_hh0 = (const float*)d_in[2];
    const float* b_ih0 = (const float*)d_in[3];
    const float* b_hh0 = (const float*)d_in[4];
    const float* w_ih1 = (const float*)d_in[5];
    const float* w_hh1 = (const float*)d_in[6];
    const float* b_ih1 = (const float*)d_in[7];
    const float* b_hh1 = (const float*)d_in[8];
    const float* w_out = (const float*)d_in[9];
    const float* b_out = (const float*)d_in[10];
    float* out = (float*)d_out;

    float *xg0, *xg1, *h1, *h, *part;
    cudaGetSymbolAddress((void**)&xg0,  g_xg0);
    cudaGetSymbolAddress((void**)&xg1,  g_xg1);
    cudaGetSymbolAddress((void**)&h1,   g_h1);
    cudaGetSymbolAddress((void**)&h,    g_h);
    cudaGetSymbolAddress((void**)&part, g_part);

    const int KSLICE = HID / SPLITK;   // 256
    const int ZSTR   = BATCH * G4;

    // 1) Layer-0 input gates: [640,4096] = input[0:640,512] @ w_ih0^T + biases
    {
        dim3 grid(G4 / BN, TSTEPS * BATCH / BM, 1);
        hmma_gemm<<<grid, NTH>>>(input, w_ih0, IN0, IN0, IN0,
                                 b_ih0, b_hh0, xg0, G4, 0);
    }
    // 2) Layer-0 recurrence
    for (int t = 0; t < TSTEPS; t++) {
        if (t > 0) {
            dim3 grid(G4 / BN, 1, SPLITK);
            hmma_gemm<<<grid, NTH>>>(h, w_hh0, HID, HID, KSLICE,
                                     (const float*)0, (const float*)0,
                                     part, G4, ZSTR);
        }
        gates_kernel<<<(BATCH * HID) / 256, 256>>>(
            xg0 + (size_t)t * BATCH * G4, h1 + (size_t)t * BATCH * HID, t == 0);
    }
    // 3) Layer-1 input gates: [640,4096] = h1 @ w_ih1^T + biases
    {
        dim3 grid(G4 / BN, TSTEPS * BATCH / BM, 1);
        hmma_gemm<<<grid, NTH>>>(h1, w_ih1, HID, HID, HID,
                                 b_ih1, b_hh1, xg1, G4, 0);
    }
    // 4) Layer-1 recurrence
    for (int t = 0; t < TSTEPS; t++) {
        if (t > 0) {
            dim3 grid(G4 / BN, 1, SPLITK);
            hmma_gemm<<<grid, NTH>>>(h, w_hh1, HID, HID, KSLICE,
                                     (const float*)0, (const float*)0,
                                     part, G4, ZSTR);
        }
        gates_kernel<<<(BATCH * HID) / 256, 256>>>(
            xg1 + (size_t)t * BATCH * G4, (float*)0, t == 0);
    }
    // 5) Linear head on h2[4]
    head_kernel<<<BATCH, 256>>>(w_out, b_out, out);
}

// round 15
// speedup vs baseline: 2.1400x; 1.0115x over previous
#include <cuda_runtime.h>
#include <cuda_fp16.h>
#include <math.h>
#include <stdint.h>

#define TSTEPS 5
#define BATCH  128
#define IN0    512
#define HID    1024
#define G4     4096
#define OUTD   32
#define SPLITK 4

#define BM 128
#define BN 128
#define BK 32
#define NTH 256
#define RS 40            // smem row stride in fp16 (32 data + 8 pad)

// Scratch (device globals; no allocations allowed)
__device__ float g_xg0[TSTEPS * BATCH * G4];
__device__ float g_xg1[TSTEPS * BATCH * G4];
__device__ float g_h1 [TSTEPS * BATCH * HID];
__device__ float g_h  [BATCH * HID];
__device__ float g_c  [BATCH * HID];
__device__ float g_part[SPLITK * BATCH * G4];

__device__ __forceinline__ uint32_t smem_u32(const void* p) {
    uint32_t a;
    asm("{ .reg .u64 t; cvta.to.shared.u64 t, %1; cvt.u32.u64 %0, t; }"
        : "=r"(a) : "l"(p));
    return a;
}

#define LDSM_X4(R, addr)                                                     \
    asm volatile("ldmatrix.sync.aligned.m8n8.x4.shared.b16 "                 \
                 "{%0,%1,%2,%3}, [%4];"                                      \
                 : "=r"((R)[0]), "=r"((R)[1]), "=r"((R)[2]), "=r"((R)[3])    \
                 : "r"(addr))
#define LDSM_X2(R, addr)                                                     \
    asm volatile("ldmatrix.sync.aligned.m8n8.x2.shared.b16 {%0,%1}, [%2];"   \
                 : "=r"((R)[0]), "=r"((R)[1]) : "r"(addr))
#define MMA_F16(D, Ar, Br)                                                   \
    asm volatile("mma.sync.aligned.m16n8k16.row.col.f32.f16.f16.f32 "        \
                 "{%0,%1,%2,%3}, {%4,%5,%6,%7}, {%8,%9}, {%0,%1,%2,%3};"     \
                 : "+f"((D)[0]), "+f"((D)[1]), "+f"((D)[2]), "+f"((D)[3])    \
                 : "r"((Ar)[0]), "r"((Ar)[1]), "r"((Ar)[2]), "r"((Ar)[3]),   \
                   "r"((Br)[0]), "r"((Br)[1]))

__device__ __forceinline__ uint16_t to_h16(float f) {
    return __half_as_ushort(__float2half_rn(f));
}
// HW tanh approximation (single MUFU instruction, sm_75+)
__device__ __forceinline__ float tanh_hw(float x) {
    float y;
    asm("tanh.approx.f32 %0, %1;" : "=f"(y) : "f"(x));
    return y;
}
// sigmoid via tanh: sig(x) = 0.5 + 0.5*tanh(x/2)
__device__ __forceinline__ float sig_hw(float x) {
    return fmaf(tanh_hw(0.5f * x), 0.5f, 0.5f);
}

// ---------------------------------------------------------------------------
// Tensor-core GEMM: C[M, N] (+bias) = A[*,K] @ W[N,K]^T
// A and W single fp16; ONE MMA per (mt, nt, k-step). (proven R14)
// ---------------------------------------------------------------------------
__global__ __launch_bounds__(NTH) void hmma_gemm(
    const float* __restrict__ A, const float* __restrict__ W,
    int strideA, int strideW, int ksize,
    const float* __restrict__ b1, const float* __restrict__ b2,
    float* __restrict__ Cbase, int ldc, int zStride)
{
    __shared__ uint16_t sA[BM * RS];
    __shared__ uint16_t sW[BN * RS];

    const int tid  = threadIdx.x;
    const int lane = tid & 31;
    const int warp = tid >> 5;
    const int wm   = warp >> 2;           // 0..1
    const int wn   = warp & 3;            // 0..3
    const int row0 = blockIdx.y * BM;
    const int col0 = blockIdx.x * BN;
    const int kbeg = blockIdx.z * ksize;
    const int nch  = ksize / BK;

    const bool isA = (tid < 128);
    const int  t2  = tid & 127;
    const float* src = isA ? (A + (size_t)row0 * strideA)
                           : (W + (size_t)col0 * strideW);
    const int sstr = isA ? strideA : strideW;
    uint16_t* dst = isA ? sA : sW;

    float4 pf[8];
    const uint32_t bA = smem_u32(sA);
    const uint32_t bW = smem_u32(sW);

    float acc[4][4][4];
#pragma unroll
    for (int i = 0; i < 4; i++)
#pragma unroll
        for (int j = 0; j < 4; j++)
#pragma unroll
            for (int v = 0; v < 4; v++) acc[i][j][v] = 0.f;

    // load chunk 0 into regs
#pragma unroll
    for (int i = 0; i < 8; i++) {
        int idx = t2 + 128 * i;           // 0..1023 float4 slots
        int r = idx >> 3, c4 = idx & 7;
        pf[i] = *(const float4*)(src + (size_t)r * sstr + kbeg + c4 * 4);
    }

    const int rl  = lane & 7;
    const int s8  = (lane >> 3) & 1;
    const int s16 = (lane >> 4) & 1;

    for (int c = 0; c < nch; c++) {
        // store regs -> smem (fp16)
#pragma unroll
        for (int i = 0; i < 8; i++) {
            int idx = t2 + 128 * i;
            int r = idx >> 3, c4 = idx & 7;
            float f[4] = {pf[i].x, pf[i].y, pf[i].z, pf[i].w};
            uint16_t a[4];
#pragma unroll
            for (int j = 0; j < 4; j++) a[j] = to_h16(f[j]);
            *(uint2*)(dst + r * RS + c4 * 4) = *(uint2*)a;
        }
        __syncthreads();

        // prefetch next chunk (overlaps MMA stream)
        if (c + 1 < nch) {
            const int kk = kbeg + (c + 1) * BK;
#pragma unroll
            for (int i = 0; i < 8; i++) {
                int idx = t2 + 128 * i;
                int r = idx >> 3, c4 = idx & 7;
                pf[i] = *(const float4*)(src + (size_t)r * sstr + kk + c4 * 4);
            }
        }

        // compute: 2 k-steps of 16, single MMA each
#pragma unroll
        for (int ks = 0; ks < 2; ks++) {
            const int k0b = (ks * 16 + s8 * 8) * 2;
            const int k0a = (ks * 16 + s16 * 8) * 2;

            uint32_t bw[4][2];
#pragma unroll
            for (int nt = 0; nt < 4; nt++) {
                uint32_t ro = (uint32_t)(wn * 32 + nt * 8 + rl) * (RS * 2) + k0b;
                LDSM_X2(bw[nt], bW + ro);
            }
#pragma unroll
            for (int mt = 0; mt < 4; mt++) {
                uint32_t ro = (uint32_t)(wm * 64 + mt * 16 + rl + s8 * 8) * (RS * 2) + k0a;
                uint32_t ah[4];
                LDSM_X4(ah, bA + ro);
#pragma unroll
                for (int nt = 0; nt < 4; nt++) MMA_F16(acc[mt][nt], ah, bw[nt]);
            }
        }
        __syncthreads();
    }

    // Epilogue: direct fragment stores (+bias)
    float* outp = Cbase + (size_t)blockIdx.z * zStride;
#pragma unroll
    for (int mt = 0; mt < 4; mt++) {
        int row = row0 + wm * 64 + mt * 16 + (lane >> 2);
#pragma unroll
        for (int nt = 0; nt < 4; nt++) {
            int col = col0 + wn * 32 + nt * 8 + (lane & 3) * 2;
            float bb0 = 0.f, bb1 = 0.f;
            if (b1) {
                bb0 = b1[col] + b2[col];
                bb1 = b1[col + 1] + b2[col + 1];
            }
            float2 v0 = make_float2(acc[mt][nt][0] + bb0, acc[mt][nt][1] + bb1);
            float2 v1 = make_float2(acc[mt][nt][2] + bb0, acc[mt][nt][3] + bb1);
            *(float2*)(outp + (size_t)row * ldc + col) = v0;
            *(float2*)(outp + (size_t)(row + 8) * ldc + col) = v1;
        }
    }
}

// ---------------------------------------------------------------------------
// Gate fusion: 512 blocks, one unit per thread; HW tanh approximations.
// g = xg + sum split-K partials; order i,f,g,o
// ---------------------------------------------------------------------------
__global__ __launch_bounds__(256) void gates_kernel(
    const float* __restrict__ xg, float* __restrict__ hseq, int first)
{
    int q = blockIdx.x * 256 + threadIdx.x;   // 0..BATCH*HID-1
    int b = q >> 10;
    int j = q & 1023;
    size_t base = (size_t)b * G4 + j;

    float gi = xg[base];
    float gf = xg[base + HID];
    float gg = xg[base + 2 * HID];
    float go = xg[base + 3 * HID];

    if (!first) {
#pragma unroll
        for (int s = 0; s < SPLITK; s++) {
            const float* P = g_part + (size_t)s * BATCH * G4 + base;
            gi += P[0];
            gf += P[HID];
            gg += P[2 * HID];
            go += P[3 * HID];
        }
    }

    int idx = b * HID + j;
    float cp = first ? 0.f : g_c[idx];
    float cn = sig_hw(gf) * cp + sig_hw(gi) * tanh_hw(gg);
    float hn = sig_hw(go) * tanh_hw(cn);
    g_c[idx] = cn;
    g_h[idx] = hn;
    if (hseq) hseq[idx] = hn;
}

// ---------------------------------------------------------------------------
// Head: out[b,o] = dot(h_final[b,:], Wout[o,:]) + bout[o]
// ---------------------------------------------------------------------------
__global__ __launch_bounds__(256) void head_kernel(
    const float* __restrict__ Wout, const float* __restrict__ bout,
    float* __restrict__ out)
{
    __shared__ float hs[HID];
    __shared__ float red[8][32];
    int b = blockIdx.x;
    for (int i = threadIdx.x; i < HID; i += 256) hs[i] = g_h[(size_t)b * HID + i];
    __syncthreads();

    int o     = threadIdx.x % 32;
    int chunk = threadIdx.x / 32;
    float s = 0.f;
    const float* wrow = Wout + (size_t)o * HID;
#pragma unroll 4
    for (int k = chunk * 128; k < chunk * 128 + 128; k++)
        s = fmaf(hs[k], wrow[k], s);
    red[chunk][o] = s;
    __syncthreads();

    if (threadIdx.x < 32) {
        float t = 0.f;
#pragma unroll
        for (int ch = 0; ch < 8; ch++) t += red[ch][threadIdx.x];
        out[(size_t)b * OUTD + threadIdx.x] = t + bout[threadIdx.x];
    }
}

// ---------------------------------------------------------------------------
// Host launcher
// ---------------------------------------------------------------------------
extern "C" void kernel_launch(void* const* d_in, const int* in_sizes, int n_in,
                              void* d_out, int out_size)
{
    const float* input = (const float*)d_in[0];
    const float* w_ih0 = (const float*)d_in[1];
    const float* w_hh0 = (const float*)d_in[2];
    const float* b_ih0 = (const float*)d_in[3];
    const float* b_hh0 = (const float*)d_in[4];
    const float* w_ih1 = (const float*)d_in[5];
    const float* w_hh1 = (const float*)d_in[6];
    const float* b_ih1 = (const float*)d_in[7];
    const float* b_hh1 = (const float*)d_in[8];
    const float* w_out = (const float*)d_in[9];
    const float* b_out = (const float*)d_in[10];
    float* out = (float*)d_out;

    float *xg0, *xg1, *h1, *h, *part;
    cudaGetSymbolAddress((void**)&xg0,  g_xg0);
    cudaGetSymbolAddress((void**)&xg1,  g_xg1);
    cudaGetSymbolAddress((void**)&h1,   g_h1);
    cudaGetSymbolAddress((void**)&h,    g_h);
    cudaGetSymbolAddress((void**)&part, g_part);

    const int KSLICE = HID / SPLITK;   // 256
    const int ZSTR   = BATCH * G4;

    // 1) Layer-0 input gates: [640,4096] = input[0:640,512] @ w_ih0^T + biases
    {
        dim3 grid(G4 / BN, TSTEPS * BATCH / BM, 1);
        hmma_gemm<<<grid, NTH>>>(input, w_ih0, IN0, IN0, IN0,
                                 b_ih0, b_hh0, xg0, G4, 0);
    }
    // 2) Layer-0 recurrence
    for (int t = 0; t < TSTEPS; t++) {
        if (t > 0) {
            dim3 grid(G4 / BN, 1, SPLITK);
            hmma_gemm<<<grid, NTH>>>(h, w_hh0, HID, HID, KSLICE,
                                     (const float*)0, (const float*)0,
                                     part, G4, ZSTR);
        }
        gates_kernel<<<(BATCH * HID) / 256, 256>>>(
            xg0 + (size_t)t * BATCH * G4, h1 + (size_t)t * BATCH * HID, t == 0);
    }
    // 3) Layer-1 input gates: [640,4096] = h1 @ w_ih1^T + biases
    {
        dim3 grid(G4 / BN, TSTEPS * BATCH / BM, 1);
        hmma_gemm<<<grid, NTH>>>(h1, w_ih1, HID, HID, HID,
                                 b_ih1, b_hh1, xg1, G4, 0);
    }
    // 4) Layer-1 recurrence
    for (int t = 0; t < TSTEPS; t++) {
        if (t > 0) {
            dim3 grid(G4 / BN, 1, SPLITK);
            hmma_gemm<<<grid, NTH>>>(h, w_hh1, HID, HID, KSLICE,
                                     (const float*)0, (const float*)0,
                                     part, G4, ZSTR);
        }
        gates_kernel<<<(BATCH * HID) / 256, 256>>>(
            xg1 + (size_t)t * BATCH * G4, (float*)0, t == 0);
    }
    // 5) Linear head on h2[4]
    head_kernel<<<BATCH, 256>>>(w_out, b_out, out);
}